// round 9
// baseline (speedup 1.0000x reference)
#include <cuda_runtime.h>
#include <cuda_bf16.h>
#include <cstdint>

// VQ_88699664597022 — bf16 mma.sync GEMM with fused candidate capture ->
// exact (round-1 arithmetic) rescore + fused gather/loss.
// out (f32): values [N*256] ++ indexes [N] ++ loss [1].

#define D_CW 256
#define K_CB 1024
#define NTOK 65536
#define MB   128          // tokens per CTA (kernel 1)
#define NCH  128          // codewords per n-chunk (8 chunks)
#define RPAD 264          // padded A/B row length (bf16) -> 528 B
#define CAP  32           // candidate capacity per token
#define DELTA_B 3.0f      // >= 2 * worst-case |approx - exact|

__device__ __align__(16) __nv_bfloat16 g_ebf[K_CB * D_CW];
__device__ float  g_enorm[K_CB];
__device__ int    g_cand[(size_t)NTOK * CAP];
__device__ int    g_ccnt[NTOK];
__device__ double g_partial[NTOK / 8];

// ------------------------------------------------ helpers
__device__ __forceinline__ uint32_t smem_u32(const void* p) {
    uint32_t a;
    asm("{ .reg .u64 t; cvta.to.shared.u64 t, %1; cvt.u32.u64 %0, t; }"
        : "=r"(a) : "l"(p));
    return a;
}
__device__ __forceinline__ void ldmatrix4(uint32_t* r, uint32_t addr) {
    asm volatile("ldmatrix.sync.aligned.m8n8.x4.shared.b16 {%0,%1,%2,%3}, [%4];"
                 : "=r"(r[0]), "=r"(r[1]), "=r"(r[2]), "=r"(r[3]) : "r"(addr));
}
__device__ __forceinline__ void mma16816(float* c, const uint32_t* a,
                                         const uint32_t* b) {
    asm volatile(
        "mma.sync.aligned.m16n8k16.row.col.f32.bf16.bf16.f32 "
        "{%0,%1,%2,%3}, {%4,%5,%6,%7}, {%8,%9}, {%0,%1,%2,%3};"
        : "+f"(c[0]), "+f"(c[1]), "+f"(c[2]), "+f"(c[3])
        : "r"(a[0]), "r"(a[1]), "r"(a[2]), "r"(a[3]), "r"(b[0]), "r"(b[1]));
}
#define CP_ASYNC16(dst, src) \
    asm volatile("cp.async.cg.shared.global [%0], [%1], 16;" \
                 :: "r"(dst), "l"(src) : "memory")
#define CP_COMMIT() asm volatile("cp.async.commit_group;" ::: "memory")
#define CP_WAIT(n)  asm volatile("cp.async.wait_group %0;" :: "n"(n) : "memory")

// ------------------------------------------------ round-1 enorm (verbatim)
__global__ void vq_enorm(const float* __restrict__ emb) {
    int k = blockIdx.x * blockDim.x + threadIdx.x;
    if (k >= K_CB) return;
    const float4* row = reinterpret_cast<const float4*>(emb + (size_t)k * D_CW);
    float s = 0.f;
#pragma unroll 16
    for (int j = 0; j < D_CW / 4; ++j) {
        float4 v = row[j];
        s += v.x * v.x + v.y * v.y + v.z * v.z + v.w * v.w;
    }
    g_enorm[k] = s;
}

__global__ void vq_prep_e(const float* __restrict__ emb) {
    int k = blockIdx.x, d = threadIdx.x;
    g_ebf[k * D_CW + d] = __float2bfloat16(emb[(size_t)k * D_CW + d]);
}

// exact round-1 rescore chain (DO NOT CHANGE: rounding correlates w/ reference)
__device__ __forceinline__ float exact_score(const float4* __restrict__ xr,
                                             const float* __restrict__ emb,
                                             int ci) {
    const float4* er = reinterpret_cast<const float4*>(emb + (size_t)ci * D_CW);
    float dot = 0.f;
#pragma unroll 8
    for (int q = 0; q < 64; ++q) {
        float4 a = xr[q], e = er[q];
        dot = fmaf(a.x, e.x, dot);
        dot = fmaf(a.y, e.y, dot);
        dot = fmaf(a.z, e.z, dot);
        dot = fmaf(a.w, e.w, dot);
    }
    return g_enorm[ci] - 2.f * dot;
}

// ------------------------------------------------ kernel 1: GEMM + capture
// smem: As [128][264] bf16 @0 (67584), Bs [2][128][264] @67584 (135168),
//       ens [1024] f32 @202752 (4096), cnt [128] int @206848 (512),
//       cand [128][32] int @207360 (16384). total 223744 B.
__global__ void __launch_bounds__(256, 1)
vq_mma_k(const float* __restrict__ x)
{
    extern __shared__ char smem[];
    __nv_bfloat16* As = (__nv_bfloat16*)smem;
    float* ens = (float*)(smem + 202752);
    int*   cnt = (int*)(smem + 206848);
    int  (*cand)[CAP] = (int(*)[CAP])(smem + 207360);
    const uint32_t sb = smem_u32(smem);
    const uint32_t sA = sb, sB = sb + 67584;

    const int tid = threadIdx.x, wid = tid >> 5, lane = tid & 31;
    const int tok0 = blockIdx.x * MB;

#pragma unroll
    for (int i = 0; i < 4; ++i) ens[tid + i * 256] = g_enorm[tid + i * 256];
    if (tid < MB) cnt[tid] = 0;

    // A: load x fp32, convert to bf16, padded rows
    {
        int row = tid >> 1, half = tid & 1;
        const float4* xr = reinterpret_cast<const float4*>(
            x + (size_t)(tok0 + row) * D_CW) + half * 32;
        __nv_bfloat16* dst = As + row * RPAD + half * 128;
#pragma unroll
        for (int q = 0; q < 16; ++q) {
            float4 v0 = xr[2 * q], v1 = xr[2 * q + 1];
            __nv_bfloat162 p0 = __floats2bfloat162_rn(v0.x, v0.y);
            __nv_bfloat162 p1 = __floats2bfloat162_rn(v0.z, v0.w);
            __nv_bfloat162 p2 = __floats2bfloat162_rn(v1.x, v1.y);
            __nv_bfloat162 p3 = __floats2bfloat162_rn(v1.z, v1.w);
            uint4 pk;
            pk.x = *(uint32_t*)&p0; pk.y = *(uint32_t*)&p1;
            pk.z = *(uint32_t*)&p2; pk.w = *(uint32_t*)&p3;
            *reinterpret_cast<uint4*>(dst + q * 8) = pk;
        }
    }

    // prefetch B chunk 0
    {
        uint32_t bbuf = sB;
#pragma unroll
        for (int t = 0; t < 16; ++t) {
            int id = tid + t * 256;
            int row = id >> 5, ck = id & 31;
            CP_ASYNC16(bbuf + row * 528 + ck * 16,
                       g_ebf + (size_t)row * D_CW + ck * 8);
        }
        CP_COMMIT();
    }

    const int tokA = wid * 16 + (lane >> 2);   // local token for acc[.][0..1]
    const int tokB = tokA + 8;                 // local token for acc[.][2..3]
    float rmA = 3.4e38f, rmB = 3.4e38f;        // lane-local running minima

    for (int nc = 0; nc < 8; ++nc) {
        if (nc < 7) {
            uint32_t bbuf = sB + ((nc + 1) & 1) * 67584;
            const __nv_bfloat16* src = g_ebf + (size_t)(nc + 1) * NCH * D_CW;
#pragma unroll
            for (int t = 0; t < 16; ++t) {
                int id = tid + t * 256;
                int row = id >> 5, ck = id & 31;
                CP_ASYNC16(bbuf + row * 528 + ck * 16,
                           src + (size_t)row * D_CW + ck * 8);
            }
            CP_COMMIT();
            CP_WAIT(1);
        } else {
            CP_WAIT(0);
        }
        __syncthreads();

        float acc[16][4];
#pragma unroll
        for (int t = 0; t < 16; ++t)
#pragma unroll
            for (int j = 0; j < 4; ++j) acc[t][j] = 0.f;

        const uint32_t bBase = sB + (nc & 1) * 67584;
        const uint32_t aRow = sA + (wid * 16 + (lane & 15)) * 528
                            + ((lane >> 4) * 8) * 2;
        const uint32_t bRowOff = ((lane & 7) + ((lane >> 4) << 3)) * 528
                               + (((lane >> 3) & 1) << 3) * 2;
#pragma unroll
        for (int kk = 0; kk < 16; ++kk) {
            uint32_t a[4];
            ldmatrix4(a, aRow + kk * 32);
#pragma unroll
            for (int nt = 0; nt < 8; ++nt) {
                uint32_t b[4];
                ldmatrix4(b, bBase + nt * 16 * 528 + bRowOff + kk * 32);
                mma16816(acc[2 * nt],     a, b);
                mma16816(acc[2 * nt + 1], a, b + 2);
            }
        }

        // epilogue: s = enorm - 2*dot; capture s <= runmin + DELTA (superset
        // of final window since runmin only decreases -> guarantee preserved)
        const int cb = nc * NCH + 2 * (lane & 3);
#pragma unroll
        for (int t = 0; t < 16; ++t) {
            int c = cb + t * 8;
            float2 e2 = *reinterpret_cast<const float2*>(ens + c);
            float s0 = fmaf(-2.f, acc[t][0], e2.x);
            float s1 = fmaf(-2.f, acc[t][1], e2.y);
            float s2 = fmaf(-2.f, acc[t][2], e2.x);
            float s3 = fmaf(-2.f, acc[t][3], e2.y);
            if (s0 <= rmA + DELTA_B) {
                int p = atomicAdd(&cnt[tokA], 1);
                if (p < CAP) cand[tokA][p] = c;
            }
            rmA = fminf(rmA, s0);
            if (s1 <= rmA + DELTA_B) {
                int p = atomicAdd(&cnt[tokA], 1);
                if (p < CAP) cand[tokA][p] = c + 1;
            }
            rmA = fminf(rmA, s1);
            if (s2 <= rmB + DELTA_B) {
                int p = atomicAdd(&cnt[tokB], 1);
                if (p < CAP) cand[tokB][p] = c;
            }
            rmB = fminf(rmB, s2);
            if (s3 <= rmB + DELTA_B) {
                int p = atomicAdd(&cnt[tokB], 1);
                if (p < CAP) cand[tokB][p] = c + 1;
            }
            rmB = fminf(rmB, s3);
        }
        __syncthreads();
    }

    // flush candidates to global
    if (tid < MB) g_ccnt[tok0 + tid] = cnt[tid];
    for (int e = tid; e < MB * CAP; e += 256) {
        int t = e / CAP, j = e % CAP;
        if (j < min(cnt[t], CAP))
            g_cand[(size_t)(tok0 + t) * CAP + j] = cand[t][j];
    }
}

// ------------------------------------------------ kernel 2: rescore + gather
// one warp per token: exact round-1 rescore of candidates, then fused
// values write + deterministic loss partial.
__global__ void __launch_bounds__(256)
vq_resc(const float* __restrict__ x, const float* __restrict__ emb,
        float* __restrict__ out, int n_tok)
{
    __shared__ double wsum[8];
    const int wp = threadIdx.x >> 5, lane = threadIdx.x & 31;
    const int token = blockIdx.x * 8 + wp;
    const float4* xr = reinterpret_cast<const float4*>(x + (size_t)token * D_CW);

    int cnt = g_ccnt[token];
    int idx;
    if (cnt == 1) {
        idx = g_cand[(size_t)token * CAP];
    } else if (cnt <= CAP) {
        float sc = 3.4e38f; int ci = 0x7FFFFFFF;
        if (lane < cnt) {
            ci = g_cand[(size_t)token * CAP + lane];
            sc = exact_score(xr, emb, ci);
        }
#pragma unroll
        for (int o = 16; o; o >>= 1) {
            float os = __shfl_xor_sync(0xffffffffu, sc, o);
            int   oi = __shfl_xor_sync(0xffffffffu, ci, o);
            if (os < sc || (os == sc && oi < ci)) { sc = os; ci = oi; }
        }
        idx = ci;
    } else {
        // overflow fallback (rare): exact rescore of all codewords
        float bs = 3.4e38f; int bi = 0x7FFFFFFF;
        for (int b0 = 0; b0 < K_CB; b0 += 32) {
            int ci = b0 + lane;
            float sc = exact_score(xr, emb, ci);
#pragma unroll
            for (int o = 16; o; o >>= 1) {
                float os = __shfl_xor_sync(0xffffffffu, sc, o);
                int   oi = __shfl_xor_sync(0xffffffffu, ci, o);
                if (os < sc || (os == sc && oi < ci)) { sc = os; ci = oi; }
            }
            if (sc < bs || (sc == bs && ci < bi)) { bs = sc; bi = ci; }
        }
        idx = bi;
    }

    // fused gather: values_st = x + (e - x), loss partial
    const float4* er = reinterpret_cast<const float4*>(emb + (size_t)idx * D_CW);
    float4* orow = reinterpret_cast<float4*>(out + (size_t)token * D_CW);
    double ls = 0.0;
#pragma unroll
    for (int q = 0; q < 2; ++q) {
        int j = lane + 32 * q;
        float4 xv = xr[j], ev = er[j];
        float4 o;
        o.x = xv.x + (ev.x - xv.x);
        o.y = xv.y + (ev.y - xv.y);
        o.z = xv.z + (ev.z - xv.z);
        o.w = xv.w + (ev.w - xv.w);
        orow[j] = o;
        float r;
        r = xv.x - ev.x; ls += (double)r * (double)r;
        r = xv.y - ev.y; ls += (double)r * (double)r;
        r = xv.z - ev.z; ls += (double)r * (double)r;
        r = xv.w - ev.w; ls += (double)r * (double)r;
    }
    if (lane == 0) out[(size_t)n_tok * D_CW + token] = (float)idx;

#pragma unroll
    for (int o = 16; o > 0; o >>= 1) ls += __shfl_down_sync(0xffffffffu, ls, o);
    if (lane == 0) wsum[wp] = ls;
    __syncthreads();
    if (threadIdx.x == 0) {
        double s = 0.0;
#pragma unroll
        for (int w = 0; w < 8; ++w) s += wsum[w];
        g_partial[blockIdx.x] = s;
    }
}

__global__ void vq_finalize(float* __restrict__ out, int nblocks,
                            long long pos, double scale) {
    __shared__ double buf[256];
    double s = 0.0;
    for (int i = threadIdx.x; i < nblocks; i += 256) s += g_partial[i];
    buf[threadIdx.x] = s;
    __syncthreads();
    for (int off = 128; off > 0; off >>= 1) {
        if (threadIdx.x < off) buf[threadIdx.x] += buf[threadIdx.x + off];
        __syncthreads();
    }
    if (threadIdx.x == 0) out[pos] = (float)(buf[0] * scale);
}

// ------------------------------------------------ launch
extern "C" void kernel_launch(void* const* d_in, const int* in_sizes, int n_in,
                              void* d_out, int out_size) {
    const float* x   = (const float*)d_in[0];
    const float* emb = (const float*)d_in[1];
    float* out = (float*)d_out;

    int nd    = in_sizes[0];    // 65536*256
    int n_tok = nd / D_CW;      // 65536

    vq_enorm<<<(K_CB + 255) / 256, 256>>>(emb);
    vq_prep_e<<<K_CB, 256>>>(emb);

    size_t shmem = 223744;
    cudaFuncSetAttribute(vq_mma_k, cudaFuncAttributeMaxDynamicSharedMemorySize,
                         (int)shmem);
    vq_mma_k<<<n_tok / MB, 256, shmem>>>(x);

    vq_resc<<<n_tok / 8, 256>>>(x, emb, out, n_tok);

    long long lpos = (long long)nd + n_tok;
    if (lpos < (long long)out_size)
        vq_finalize<<<1, 256>>>(out, n_tok / 8, lpos, 1.1 / (double)nd);
}

// round 12
// speedup vs baseline: 21.3541x; 21.3541x over previous
#include <cuda_runtime.h>
#include <cuda_bf16.h>
#include <cstdint>

// VQ_88699664597022 — bf16 mma.sync GEMM -> score materialization ->
// coalesced guaranteed-shortlist select fused with gather/loss.
// out (f32): values [N*256] ++ indexes [N] ++ loss [1].

#define D_CW 256
#define K_CB 1024
#define NTOK 65536
#define MB   128          // tokens per CTA (kernel 1)
#define NCH  128          // codewords per n-chunk (8 chunks)
#define RPAD 264          // padded A/B row length (bf16) -> 528 B

__device__ __align__(16) __nv_bfloat16 g_ebf[K_CB * D_CW];
__device__ float  g_enorm[K_CB];
__device__ float  g_S[(size_t)NTOK * K_CB];   // approx scores, 268 MB
__device__ double g_partial[NTOK / 8];

// ------------------------------------------------ helpers
__device__ __forceinline__ uint32_t smem_u32(const void* p) {
    uint32_t a;
    asm("{ .reg .u64 t; cvta.to.shared.u64 t, %1; cvt.u32.u64 %0, t; }"
        : "=r"(a) : "l"(p));
    return a;
}
__device__ __forceinline__ void ldmatrix4(uint32_t* r, uint32_t addr) {
    asm volatile("ldmatrix.sync.aligned.m8n8.x4.shared.b16 {%0,%1,%2,%3}, [%4];"
                 : "=r"(r[0]), "=r"(r[1]), "=r"(r[2]), "=r"(r[3]) : "r"(addr));
}
__device__ __forceinline__ void mma16816(float* c, const uint32_t* a,
                                         const uint32_t* b) {
    asm volatile(
        "mma.sync.aligned.m16n8k16.row.col.f32.bf16.bf16.f32 "
        "{%0,%1,%2,%3}, {%4,%5,%6,%7}, {%8,%9}, {%0,%1,%2,%3};"
        : "+f"(c[0]), "+f"(c[1]), "+f"(c[2]), "+f"(c[3])
        : "r"(a[0]), "r"(a[1]), "r"(a[2]), "r"(a[3]), "r"(b[0]), "r"(b[1]));
}
#define CP_ASYNC16(dst, src) \
    asm volatile("cp.async.cg.shared.global [%0], [%1], 16;" \
                 :: "r"(dst), "l"(src) : "memory")
#define CP_COMMIT() asm volatile("cp.async.commit_group;" ::: "memory")
#define CP_WAIT(n)  asm volatile("cp.async.wait_group %0;" :: "n"(n) : "memory")

// ------------------------------------------------ round-1 enorm (verbatim)
__global__ void vq_enorm(const float* __restrict__ emb) {
    int k = blockIdx.x * blockDim.x + threadIdx.x;
    if (k >= K_CB) return;
    const float4* row = reinterpret_cast<const float4*>(emb + (size_t)k * D_CW);
    float s = 0.f;
#pragma unroll 16
    for (int j = 0; j < D_CW / 4; ++j) {
        float4 v = row[j];
        s += v.x * v.x + v.y * v.y + v.z * v.z + v.w * v.w;
    }
    g_enorm[k] = s;
}

__global__ void vq_prep_e(const float* __restrict__ emb) {
    int k = blockIdx.x, d = threadIdx.x;
    g_ebf[k * D_CW + d] = __float2bfloat16(emb[(size_t)k * D_CW + d]);
}

// ------------------------------------------------ kernel 1: GEMM, write S
// (byte-identical structure to round 8 — known 230 us, known correct)
// smem: As [128][264] bf16 @0 (67584 B), Bs [2][128][264] @67584 (135168 B),
//       ens [1024] f32 @202752 (4096 B). total 206848 B.
__global__ void __launch_bounds__(256, 1)
vq_mma_k(const float* __restrict__ x)
{
    extern __shared__ char smem[];
    __nv_bfloat16* As = (__nv_bfloat16*)smem;
    float* ens = (float*)(smem + 202752);
    const uint32_t sb = smem_u32(smem);
    const uint32_t sA = sb, sB = sb + 67584;

    const int tid = threadIdx.x, wid = tid >> 5, lane = tid & 31;
    const int tok0 = blockIdx.x * MB;

#pragma unroll
    for (int i = 0; i < 4; ++i) ens[tid + i * 256] = g_enorm[tid + i * 256];

    // A: load x fp32, convert to bf16, padded rows
    {
        int row = tid >> 1, half = tid & 1;
        const float4* xr = reinterpret_cast<const float4*>(
            x + (size_t)(tok0 + row) * D_CW) + half * 32;
        __nv_bfloat16* dst = As + row * RPAD + half * 128;
#pragma unroll
        for (int q = 0; q < 16; ++q) {
            float4 v0 = xr[2 * q], v1 = xr[2 * q + 1];
            __nv_bfloat162 p0 = __floats2bfloat162_rn(v0.x, v0.y);
            __nv_bfloat162 p1 = __floats2bfloat162_rn(v0.z, v0.w);
            __nv_bfloat162 p2 = __floats2bfloat162_rn(v1.x, v1.y);
            __nv_bfloat162 p3 = __floats2bfloat162_rn(v1.z, v1.w);
            uint4 pk;
            pk.x = *(uint32_t*)&p0; pk.y = *(uint32_t*)&p1;
            pk.z = *(uint32_t*)&p2; pk.w = *(uint32_t*)&p3;
            *reinterpret_cast<uint4*>(dst + q * 8) = pk;
        }
    }

    // prefetch B chunk 0
    {
        uint32_t bbuf = sB;
#pragma unroll
        for (int t = 0; t < 16; ++t) {
            int id = tid + t * 256;
            int row = id >> 5, ck = id & 31;
            CP_ASYNC16(bbuf + row * 528 + ck * 16,
                       g_ebf + (size_t)row * D_CW + ck * 8);
        }
        CP_COMMIT();
    }

    const int rowA = tok0 + wid * 16 + (lane >> 2);      // acc[.][0..1]
    float* SrowA = g_S + (size_t)rowA * K_CB;
    float* SrowB = SrowA + (size_t)8 * K_CB;             // acc[.][2..3]

    for (int nc = 0; nc < 8; ++nc) {
        if (nc < 7) {
            uint32_t bbuf = sB + ((nc + 1) & 1) * 67584;
            const __nv_bfloat16* src = g_ebf + (size_t)(nc + 1) * NCH * D_CW;
#pragma unroll
            for (int t = 0; t < 16; ++t) {
                int id = tid + t * 256;
                int row = id >> 5, ck = id & 31;
                CP_ASYNC16(bbuf + row * 528 + ck * 16,
                           src + (size_t)row * D_CW + ck * 8);
            }
            CP_COMMIT();
            CP_WAIT(1);
        } else {
            CP_WAIT(0);
        }
        __syncthreads();

        float acc[16][4];
#pragma unroll
        for (int t = 0; t < 16; ++t)
#pragma unroll
            for (int j = 0; j < 4; ++j) acc[t][j] = 0.f;

        const uint32_t bBase = sB + (nc & 1) * 67584;
        const uint32_t aRow = sA + (wid * 16 + (lane & 15)) * 528
                            + ((lane >> 4) * 8) * 2;
        const uint32_t bRowOff = ((lane & 7) + ((lane >> 4) << 3)) * 528
                               + (((lane >> 3) & 1) << 3) * 2;
#pragma unroll
        for (int kk = 0; kk < 16; ++kk) {
            uint32_t a[4];
            ldmatrix4(a, aRow + kk * 32);
#pragma unroll
            for (int nt = 0; nt < 8; ++nt) {
                uint32_t b[4];
                ldmatrix4(b, bBase + nt * 16 * 528 + bRowOff + kk * 32);
                mma16816(acc[2 * nt],     a, b);
                mma16816(acc[2 * nt + 1], a, b + 2);
            }
        }

        // epilogue: s = enorm - 2*dot -> g_S
        const int cb = nc * NCH + 2 * (lane & 3);
#pragma unroll
        for (int t = 0; t < 16; ++t) {
            int c = cb + t * 8;
            float2 e2 = *reinterpret_cast<const float2*>(ens + c);
            float2 sa, sbv;
            sa.x  = fmaf(-2.f, acc[t][0], e2.x);
            sa.y  = fmaf(-2.f, acc[t][1], e2.y);
            sbv.x = fmaf(-2.f, acc[t][2], e2.x);
            sbv.y = fmaf(-2.f, acc[t][3], e2.y);
            *reinterpret_cast<float2*>(SrowA + c) = sa;
            *reinterpret_cast<float2*>(SrowB + c) = sbv;
        }
        __syncthreads();
    }
}

// ------------------------------------------------ kernel 2: select + gather
// Coalesced score reads (512 B contiguous per load instruction), guaranteed
// DELTA shortlist, round-1 exact rescore, fused values write + loss partial.
#define DELTA_B 3.0f
__global__ void __launch_bounds__(256)
vq_select(const float* __restrict__ x, const float* __restrict__ emb,
          float* __restrict__ out, int n_tok)
{
    __shared__ int s_cnt[8];
    __shared__ int s_cand[8][128];
    __shared__ double wsum[8];
    const int wp = threadIdx.x >> 5, lane = threadIdx.x & 31;
    const int token = blockIdx.x * 8 + wp;

    // coalesced: instruction j covers bytes [j*512, j*512+512) of the row
    const float4* S4 = reinterpret_cast<const float4*>(g_S + (size_t)token * K_CB);
    float4 sv[8];
    float vmin = 3.4e38f;
#pragma unroll
    for (int j = 0; j < 8; ++j) {
        sv[j] = S4[j * 32 + lane];
        vmin = fminf(vmin, fminf(fminf(sv[j].x, sv[j].y), fminf(sv[j].z, sv[j].w)));
    }
#pragma unroll
    for (int o = 16; o; o >>= 1)
        vmin = fminf(vmin, __shfl_xor_sync(0xffffffffu, vmin, o));

    if (lane == 0) s_cnt[wp] = 0;
    __syncwarp();
    const float thr = vmin + DELTA_B;
#pragma unroll
    for (int j = 0; j < 8; ++j) {
        int base = (j * 32 + lane) * 4;
        if (sv[j].x < thr) { int p = atomicAdd(&s_cnt[wp], 1); if (p < 128) s_cand[wp][p] = base; }
        if (sv[j].y < thr) { int p = atomicAdd(&s_cnt[wp], 1); if (p < 128) s_cand[wp][p] = base + 1; }
        if (sv[j].z < thr) { int p = atomicAdd(&s_cnt[wp], 1); if (p < 128) s_cand[wp][p] = base + 2; }
        if (sv[j].w < thr) { int p = atomicAdd(&s_cnt[wp], 1); if (p < 128) s_cand[wp][p] = base + 3; }
    }
    __syncwarp();
    int nc = min(s_cnt[wp], 128);

    const float4* xr = reinterpret_cast<const float4*>(x + (size_t)token * D_CW);
    int idx;
    if (nc == 1) {
        idx = s_cand[wp][0];
    } else {
        float bs = 3.4e38f; int bi = 0x7FFFFFFF;
        for (int b0 = 0; b0 < nc; b0 += 32) {
            int li = b0 + lane;
            float sc = 3.4e38f; int ci = 0x7FFFFFFF;
            if (li < nc) {
                ci = s_cand[wp][li];
                const float4* er = reinterpret_cast<const float4*>(
                    emb + (size_t)ci * D_CW);
                float dot = 0.f;
#pragma unroll 8
                for (int q = 0; q < 64; ++q) {
                    float4 a = xr[q], e = er[q];
                    dot = fmaf(a.x, e.x, dot);
                    dot = fmaf(a.y, e.y, dot);
                    dot = fmaf(a.z, e.z, dot);
                    dot = fmaf(a.w, e.w, dot);
                }
                sc = g_enorm[ci] - 2.f * dot;
            }
#pragma unroll
            for (int o = 16; o; o >>= 1) {
                float os = __shfl_xor_sync(0xffffffffu, sc, o);
                int   oi = __shfl_xor_sync(0xffffffffu, ci, o);
                if (os < sc || (os == sc && oi < ci)) { sc = os; ci = oi; }
            }
            if (sc < bs || (sc == bs && ci < bi)) { bs = sc; bi = ci; }
        }
        idx = bi;
    }

    // fused gather: values_st = x + (e - x), deterministic loss partial
    const float4* er = reinterpret_cast<const float4*>(emb + (size_t)idx * D_CW);
    float4* orow = reinterpret_cast<float4*>(out + (size_t)token * D_CW);
    double ls = 0.0;
#pragma unroll
    for (int q = 0; q < 2; ++q) {
        int j = lane + 32 * q;
        float4 xv = xr[j], ev = er[j];
        float4 o;
        o.x = xv.x + (ev.x - xv.x);
        o.y = xv.y + (ev.y - xv.y);
        o.z = xv.z + (ev.z - xv.z);
        o.w = xv.w + (ev.w - xv.w);
        orow[j] = o;
        float r;
        r = xv.x - ev.x; ls += (double)r * (double)r;
        r = xv.y - ev.y; ls += (double)r * (double)r;
        r = xv.z - ev.z; ls += (double)r * (double)r;
        r = xv.w - ev.w; ls += (double)r * (double)r;
    }
    if (lane == 0) out[(size_t)n_tok * D_CW + token] = (float)idx;

#pragma unroll
    for (int o = 16; o > 0; o >>= 1) ls += __shfl_down_sync(0xffffffffu, ls, o);
    if (lane == 0) wsum[wp] = ls;
    __syncthreads();
    if (threadIdx.x == 0) {
        double s = 0.0;
#pragma unroll
        for (int w = 0; w < 8; ++w) s += wsum[w];
        g_partial[blockIdx.x] = s;
    }
}

__global__ void vq_finalize(float* __restrict__ out, int nblocks,
                            long long pos, double scale) {
    __shared__ double buf[256];
    double s = 0.0;
    for (int i = threadIdx.x; i < nblocks; i += 256) s += g_partial[i];
    buf[threadIdx.x] = s;
    __syncthreads();
    for (int off = 128; off > 0; off >>= 1) {
        if (threadIdx.x < off) buf[threadIdx.x] += buf[threadIdx.x + off];
        __syncthreads();
    }
    if (threadIdx.x == 0) out[pos] = (float)(buf[0] * scale);
}

// ------------------------------------------------ launch
extern "C" void kernel_launch(void* const* d_in, const int* in_sizes, int n_in,
                              void* d_out, int out_size) {
    const float* x   = (const float*)d_in[0];
    const float* emb = (const float*)d_in[1];
    float* out = (float*)d_out;

    int nd    = in_sizes[0];    // 65536*256
    int n_tok = nd / D_CW;      // 65536

    vq_enorm<<<(K_CB + 255) / 256, 256>>>(emb);
    vq_prep_e<<<K_CB, 256>>>(emb);

    size_t shmem = 206848;
    cudaFuncSetAttribute(vq_mma_k, cudaFuncAttributeMaxDynamicSharedMemorySize,
                         (int)shmem);
    vq_mma_k<<<n_tok / MB, 256, shmem>>>(x);

    vq_select<<<n_tok / 8, 256>>>(x, emb, out, n_tok);

    long long lpos = (long long)nd + n_tok;
    if (lpos < (long long)out_size)
        vq_finalize<<<1, 256>>>(out, n_tok / 8, lpos, 1.1 / (double)nd);
}

// round 13
// speedup vs baseline: 23.3427x; 1.0931x over previous
#include <cuda_runtime.h>
#include <cuda_bf16.h>
#include <cuda_fp16.h>
#include <cstdint>

// VQ_88699664597022 — bf16 mma.sync GEMM -> fp16 score materialization ->
// coalesced guaranteed-shortlist select fused with gather/loss.
// out (f32): values [N*256] ++ indexes [N] ++ loss [1].

#define D_CW 256
#define K_CB 1024
#define NTOK 65536
#define MB   128          // tokens per CTA (kernel 1)
#define NCH  128          // codewords per n-chunk (8 chunks)
#define RPAD 264          // padded A/B row length (bf16) -> 528 B

__device__ __align__(16) __nv_bfloat16 g_ebf[K_CB * D_CW];
__device__ float  g_enorm[K_CB];
__device__ __align__(16) __half g_S[(size_t)NTOK * K_CB];  // approx scores, 134 MB
__device__ double g_partial[NTOK / 8];

// ------------------------------------------------ helpers
__device__ __forceinline__ uint32_t smem_u32(const void* p) {
    uint32_t a;
    asm("{ .reg .u64 t; cvta.to.shared.u64 t, %1; cvt.u32.u64 %0, t; }"
        : "=r"(a) : "l"(p));
    return a;
}
__device__ __forceinline__ void ldmatrix4(uint32_t* r, uint32_t addr) {
    asm volatile("ldmatrix.sync.aligned.m8n8.x4.shared.b16 {%0,%1,%2,%3}, [%4];"
                 : "=r"(r[0]), "=r"(r[1]), "=r"(r[2]), "=r"(r[3]) : "r"(addr));
}
__device__ __forceinline__ void mma16816(float* c, const uint32_t* a,
                                         const uint32_t* b) {
    asm volatile(
        "mma.sync.aligned.m16n8k16.row.col.f32.bf16.bf16.f32 "
        "{%0,%1,%2,%3}, {%4,%5,%6,%7}, {%8,%9}, {%0,%1,%2,%3};"
        : "+f"(c[0]), "+f"(c[1]), "+f"(c[2]), "+f"(c[3])
        : "r"(a[0]), "r"(a[1]), "r"(a[2]), "r"(a[3]), "r"(b[0]), "r"(b[1]));
}
#define CP_ASYNC16(dst, src) \
    asm volatile("cp.async.cg.shared.global [%0], [%1], 16;" \
                 :: "r"(dst), "l"(src) : "memory")
#define CP_COMMIT() asm volatile("cp.async.commit_group;" ::: "memory")
#define CP_WAIT(n)  asm volatile("cp.async.wait_group %0;" :: "n"(n) : "memory")

// ------------------------------------------------ round-1 enorm (verbatim)
__global__ void vq_enorm(const float* __restrict__ emb) {
    int k = blockIdx.x * blockDim.x + threadIdx.x;
    if (k >= K_CB) return;
    const float4* row = reinterpret_cast<const float4*>(emb + (size_t)k * D_CW);
    float s = 0.f;
#pragma unroll 16
    for (int j = 0; j < D_CW / 4; ++j) {
        float4 v = row[j];
        s += v.x * v.x + v.y * v.y + v.z * v.z + v.w * v.w;
    }
    g_enorm[k] = s;
}

__global__ void vq_prep_e(const float* __restrict__ emb) {
    int k = blockIdx.x, d = threadIdx.x;
    g_ebf[k * D_CW + d] = __float2bfloat16(emb[(size_t)k * D_CW + d]);
}

// ------------------------------------------------ kernel 1: GEMM, write S(fp16)
// mainloop byte-identical to round 8/12; only the epilogue store narrows.
// smem: As [128][264] bf16 @0 (67584 B), Bs [2][128][264] @67584 (135168 B),
//       ens [1024] f32 @202752 (4096 B). total 206848 B.
__global__ void __launch_bounds__(256, 1)
vq_mma_k(const float* __restrict__ x)
{
    extern __shared__ char smem[];
    __nv_bfloat16* As = (__nv_bfloat16*)smem;
    float* ens = (float*)(smem + 202752);
    const uint32_t sb = smem_u32(smem);
    const uint32_t sA = sb, sB = sb + 67584;

    const int tid = threadIdx.x, wid = tid >> 5, lane = tid & 31;
    const int tok0 = blockIdx.x * MB;

#pragma unroll
    for (int i = 0; i < 4; ++i) ens[tid + i * 256] = g_enorm[tid + i * 256];

    // A: load x fp32, convert to bf16, padded rows
    {
        int row = tid >> 1, half = tid & 1;
        const float4* xr = reinterpret_cast<const float4*>(
            x + (size_t)(tok0 + row) * D_CW) + half * 32;
        __nv_bfloat16* dst = As + row * RPAD + half * 128;
#pragma unroll
        for (int q = 0; q < 16; ++q) {
            float4 v0 = xr[2 * q], v1 = xr[2 * q + 1];
            __nv_bfloat162 p0 = __floats2bfloat162_rn(v0.x, v0.y);
            __nv_bfloat162 p1 = __floats2bfloat162_rn(v0.z, v0.w);
            __nv_bfloat162 p2 = __floats2bfloat162_rn(v1.x, v1.y);
            __nv_bfloat162 p3 = __floats2bfloat162_rn(v1.z, v1.w);
            uint4 pk;
            pk.x = *(uint32_t*)&p0; pk.y = *(uint32_t*)&p1;
            pk.z = *(uint32_t*)&p2; pk.w = *(uint32_t*)&p3;
            *reinterpret_cast<uint4*>(dst + q * 8) = pk;
        }
    }

    // prefetch B chunk 0
    {
        uint32_t bbuf = sB;
#pragma unroll
        for (int t = 0; t < 16; ++t) {
            int id = tid + t * 256;
            int row = id >> 5, ck = id & 31;
            CP_ASYNC16(bbuf + row * 528 + ck * 16,
                       g_ebf + (size_t)row * D_CW + ck * 8);
        }
        CP_COMMIT();
    }

    const int rowA = tok0 + wid * 16 + (lane >> 2);      // acc[.][0..1]
    __half* SrowA = g_S + (size_t)rowA * K_CB;
    __half* SrowB = SrowA + (size_t)8 * K_CB;            // acc[.][2..3]

    for (int nc = 0; nc < 8; ++nc) {
        if (nc < 7) {
            uint32_t bbuf = sB + ((nc + 1) & 1) * 67584;
            const __nv_bfloat16* src = g_ebf + (size_t)(nc + 1) * NCH * D_CW;
#pragma unroll
            for (int t = 0; t < 16; ++t) {
                int id = tid + t * 256;
                int row = id >> 5, ck = id & 31;
                CP_ASYNC16(bbuf + row * 528 + ck * 16,
                           src + (size_t)row * D_CW + ck * 8);
            }
            CP_COMMIT();
            CP_WAIT(1);
        } else {
            CP_WAIT(0);
        }
        __syncthreads();

        float acc[16][4];
#pragma unroll
        for (int t = 0; t < 16; ++t)
#pragma unroll
            for (int j = 0; j < 4; ++j) acc[t][j] = 0.f;

        const uint32_t bBase = sB + (nc & 1) * 67584;
        const uint32_t aRow = sA + (wid * 16 + (lane & 15)) * 528
                            + ((lane >> 4) * 8) * 2;
        const uint32_t bRowOff = ((lane & 7) + ((lane >> 4) << 3)) * 528
                               + (((lane >> 3) & 1) << 3) * 2;
#pragma unroll
        for (int kk = 0; kk < 16; ++kk) {
            uint32_t a[4];
            ldmatrix4(a, aRow + kk * 32);
#pragma unroll
            for (int nt = 0; nt < 8; ++nt) {
                uint32_t b[4];
                ldmatrix4(b, bBase + nt * 16 * 528 + bRowOff + kk * 32);
                mma16816(acc[2 * nt],     a, b);
                mma16816(acc[2 * nt + 1], a, b + 2);
            }
        }

        // epilogue: s = enorm - 2*dot -> g_S (fp16 pairs)
        const int cb = nc * NCH + 2 * (lane & 3);
#pragma unroll
        for (int t = 0; t < 16; ++t) {
            int c = cb + t * 8;
            float2 e2 = *reinterpret_cast<const float2*>(ens + c);
            __half2 ha = __floats2half2_rn(fmaf(-2.f, acc[t][0], e2.x),
                                           fmaf(-2.f, acc[t][1], e2.y));
            __half2 hb = __floats2half2_rn(fmaf(-2.f, acc[t][2], e2.x),
                                           fmaf(-2.f, acc[t][3], e2.y));
            *reinterpret_cast<__half2*>(SrowA + c) = ha;
            *reinterpret_cast<__half2*>(SrowB + c) = hb;
        }
        __syncthreads();
    }
}

// ------------------------------------------------ kernel 2: select + gather
// Coalesced fp16 score reads, guaranteed DELTA shortlist, round-1 exact
// rescore, fused values write + loss partial.
#define DELTA_B 3.5f     // >= 2 * (1.4 GEMM bound + 0.25 fp16 storage bound)
__global__ void __launch_bounds__(256)
vq_select(const float* __restrict__ x, const float* __restrict__ emb,
          float* __restrict__ out, int n_tok)
{
    __shared__ int s_cnt[8];
    __shared__ int s_cand[8][128];
    __shared__ double wsum[8];
    const int wp = threadIdx.x >> 5, lane = threadIdx.x & 31;
    const int token = blockIdx.x * 8 + wp;

    // coalesced: load j covers bytes [j*512, j*512+512) of the 2 KB row
    const uint4* S4 = reinterpret_cast<const uint4*>(g_S + (size_t)token * K_CB);
    uint4 sv[4];
#pragma unroll
    for (int j = 0; j < 4; ++j) sv[j] = S4[j * 32 + lane];

    // min over 32 halves via hmin2 tree
    __half2 m2 = __floats2half2_rn(3.0e4f, 3.0e4f);
#pragma unroll
    for (int j = 0; j < 4; ++j) {
        m2 = __hmin2(m2, *reinterpret_cast<__half2*>(&sv[j].x));
        m2 = __hmin2(m2, *reinterpret_cast<__half2*>(&sv[j].y));
        m2 = __hmin2(m2, *reinterpret_cast<__half2*>(&sv[j].z));
        m2 = __hmin2(m2, *reinterpret_cast<__half2*>(&sv[j].w));
    }
    float2 mf = __half22float2(m2);
    float vmin = fminf(mf.x, mf.y);
#pragma unroll
    for (int o = 16; o; o >>= 1)
        vmin = fminf(vmin, __shfl_xor_sync(0xffffffffu, vmin, o));

    if (lane == 0) s_cnt[wp] = 0;
    __syncwarp();
    const float thr = vmin + DELTA_B;
#pragma unroll
    for (int j = 0; j < 4; ++j) {
        const uint32_t w[4] = { sv[j].x, sv[j].y, sv[j].z, sv[j].w };
#pragma unroll
        for (int q = 0; q < 4; ++q) {
            float2 f = __half22float2(*reinterpret_cast<const __half2*>(&w[q]));
            int base = (j * 32 + lane) * 8 + q * 2;
            if (f.x < thr) { int p = atomicAdd(&s_cnt[wp], 1); if (p < 128) s_cand[wp][p] = base; }
            if (f.y < thr) { int p = atomicAdd(&s_cnt[wp], 1); if (p < 128) s_cand[wp][p] = base + 1; }
        }
    }
    __syncwarp();
    int nc = min(s_cnt[wp], 128);

    const float4* xr = reinterpret_cast<const float4*>(x + (size_t)token * D_CW);
    int idx;
    if (nc == 1) {
        idx = s_cand[wp][0];
    } else {
        float bs = 3.4e38f; int bi = 0x7FFFFFFF;
        for (int b0 = 0; b0 < nc; b0 += 32) {
            int li = b0 + lane;
            float sc = 3.4e38f; int ci = 0x7FFFFFFF;
            if (li < nc) {
                ci = s_cand[wp][li];
                const float4* er = reinterpret_cast<const float4*>(
                    emb + (size_t)ci * D_CW);
                float dot = 0.f;
#pragma unroll 8
                for (int q = 0; q < 64; ++q) {
                    float4 a = xr[q], e = er[q];
                    dot = fmaf(a.x, e.x, dot);
                    dot = fmaf(a.y, e.y, dot);
                    dot = fmaf(a.z, e.z, dot);
                    dot = fmaf(a.w, e.w, dot);
                }
                sc = g_enorm[ci] - 2.f * dot;
            }
#pragma unroll
            for (int o = 16; o; o >>= 1) {
                float os = __shfl_xor_sync(0xffffffffu, sc, o);
                int   oi = __shfl_xor_sync(0xffffffffu, ci, o);
                if (os < sc || (os == sc && oi < ci)) { sc = os; ci = oi; }
            }
            if (sc < bs || (sc == bs && ci < bi)) { bs = sc; bi = ci; }
        }
        idx = bi;
    }

    // fused gather: values_st = x + (e - x), deterministic loss partial
    const float4* er = reinterpret_cast<const float4*>(emb + (size_t)idx * D_CW);
    float4* orow = reinterpret_cast<float4*>(out + (size_t)token * D_CW);
    double ls = 0.0;
#pragma unroll
    for (int q = 0; q < 2; ++q) {
        int j = lane + 32 * q;
        float4 xv = xr[j], ev = er[j];
        float4 o;
        o.x = xv.x + (ev.x - xv.x);
        o.y = xv.y + (ev.y - xv.y);
        o.z = xv.z + (ev.z - xv.z);
        o.w = xv.w + (ev.w - xv.w);
        orow[j] = o;
        float r;
        r = xv.x - ev.x; ls += (double)r * (double)r;
        r = xv.y - ev.y; ls += (double)r * (double)r;
        r = xv.z - ev.z; ls += (double)r * (double)r;
        r = xv.w - ev.w; ls += (double)r * (double)r;
    }
    if (lane == 0) out[(size_t)n_tok * D_CW + token] = (float)idx;

#pragma unroll
    for (int o = 16; o > 0; o >>= 1) ls += __shfl_down_sync(0xffffffffu, ls, o);
    if (lane == 0) wsum[wp] = ls;
    __syncthreads();
    if (threadIdx.x == 0) {
        double s = 0.0;
#pragma unroll
        for (int w = 0; w < 8; ++w) s += wsum[w];
        g_partial[blockIdx.x] = s;
    }
}

__global__ void vq_finalize(float* __restrict__ out, int nblocks,
                            long long pos, double scale) {
    __shared__ double buf[256];
    double s = 0.0;
    for (int i = threadIdx.x; i < nblocks; i += 256) s += g_partial[i];
    buf[threadIdx.x] = s;
    __syncthreads();
    for (int off = 128; off > 0; off >>= 1) {
        if (threadIdx.x < off) buf[threadIdx.x] += buf[threadIdx.x + off];
        __syncthreads();
    }
    if (threadIdx.x == 0) out[pos] = (float)(buf[0] * scale);
}

// ------------------------------------------------ launch
extern "C" void kernel_launch(void* const* d_in, const int* in_sizes, int n_in,
                              void* d_out, int out_size) {
    const float* x   = (const float*)d_in[0];
    const float* emb = (const float*)d_in[1];
    float* out = (float*)d_out;

    int nd    = in_sizes[0];    // 65536*256
    int n_tok = nd / D_CW;      // 65536

    vq_enorm<<<(K_CB + 255) / 256, 256>>>(emb);
    vq_prep_e<<<K_CB, 256>>>(emb);

    size_t shmem = 206848;
    cudaFuncSetAttribute(vq_mma_k, cudaFuncAttributeMaxDynamicSharedMemorySize,
                         (int)shmem);
    vq_mma_k<<<n_tok / MB, 256, shmem>>>(x);

    vq_select<<<n_tok / 8, 256>>>(x, emb, out, n_tok);

    long long lpos = (long long)nd + n_tok;
    if (lpos < (long long)out_size)
        vq_finalize<<<1, 256>>>(out, n_tok / 8, lpos, 1.1 / (double)nd);
}